// round 1
// baseline (speedup 1.0000x reference)
#include <cuda_runtime.h>
#include <math.h>

#define D_MODEL 1024
#define NH 16
#define DH 64
#define BB 2
#define SS 2048
#define MTOT (BB * SS)          // 4096
#define QKV_W (3 * D_MODEL)     // 3072

// Scratch (device globals: allocation-free)
__device__ float g_qkv[(size_t)MTOT * QKV_W];    // [b, s, {q|k|v}, h, dh]
__device__ float g_att[(size_t)MTOT * D_MODEL];  // attention output pre-proj

// ---------------------------------------------------------------------------
// SGEMM: C[M,N] = A[M,K] @ W[N,K]^T + bias[N]
// BM=BN=128, BK=8, TM=TN=8, 256 threads. All dims divisible -> no bounds checks.
// ---------------------------------------------------------------------------
__global__ __launch_bounds__(256)
void sgemm_nt_bias(const float* __restrict__ A, const float* __restrict__ W,
                   const float* __restrict__ bias, float* __restrict__ C,
                   int M, int N, int K) {
    __shared__ __align__(16) float As[8][132];
    __shared__ __align__(16) float Bs[8][132];

    const int tid = threadIdx.x;
    const int tx = tid & 15;        // 0..15 (col group)
    const int ty = tid >> 4;        // 0..15 (row group)
    const int bm = blockIdx.y * 128;
    const int bn = blockIdx.x * 128;

    const int lr = tid >> 1;        // 0..127 row in tile
    const int lc = (tid & 1) * 4;   // 0 or 4

    float acc[8][8];
#pragma unroll
    for (int i = 0; i < 8; i++)
#pragma unroll
        for (int j = 0; j < 8; j++) acc[i][j] = 0.f;

    const float* Arow = A + (size_t)(bm + lr) * K + lc;
    const float* Wrow = W + (size_t)(bn + lr) * K + lc;

    for (int k0 = 0; k0 < K; k0 += 8) {
        float4 av = *(const float4*)(Arow + k0);
        float4 wv = *(const float4*)(Wrow + k0);
        As[lc + 0][lr] = av.x; As[lc + 1][lr] = av.y;
        As[lc + 2][lr] = av.z; As[lc + 3][lr] = av.w;
        Bs[lc + 0][lr] = wv.x; Bs[lc + 1][lr] = wv.y;
        Bs[lc + 2][lr] = wv.z; Bs[lc + 3][lr] = wv.w;
        __syncthreads();
#pragma unroll
        for (int k = 0; k < 8; k++) {
            float ar[8], br[8];
            *(float4*)&ar[0] = *(const float4*)&As[k][ty * 8];
            *(float4*)&ar[4] = *(const float4*)&As[k][ty * 8 + 4];
            *(float4*)&br[0] = *(const float4*)&Bs[k][tx * 8];
            *(float4*)&br[4] = *(const float4*)&Bs[k][tx * 8 + 4];
#pragma unroll
            for (int i = 0; i < 8; i++)
#pragma unroll
                for (int j = 0; j < 8; j++)
                    acc[i][j] = fmaf(ar[i], br[j], acc[i][j]);
        }
        __syncthreads();
    }

#pragma unroll
    for (int i = 0; i < 8; i++) {
        float* crow = C + (size_t)(bm + ty * 8 + i) * N + bn + tx * 8;
        const float* brow = bias + bn + tx * 8;
#pragma unroll
        for (int j = 0; j < 8; j += 4) {
            float4 v;
            v.x = acc[i][j + 0] + brow[j + 0];
            v.y = acc[i][j + 1] + brow[j + 1];
            v.z = acc[i][j + 2] + brow[j + 2];
            v.w = acc[i][j + 3] + brow[j + 3];
            *(float4*)&crow[j] = v;
        }
    }
}

// ---------------------------------------------------------------------------
// Flash attention (causal), fp32. Block: 64 query rows of one (b,h).
// 128 threads: 2 threads per query row (half 0 -> key cols 0..31, half 1 -> 32..63).
// K and V share one smem buffer (V loaded after scores) to stay < 48 KB.
// ---------------------------------------------------------------------------
__global__ __launch_bounds__(128)
void attn_kernel() {
    __shared__ __align__(16) float Qs[64][68];
    __shared__ __align__(16) float KVs[64][68];

    const int tid  = threadIdx.x;
    const int row  = tid >> 1;
    const int half = tid & 1;
    const int col0 = half * 32;
    const int qt = blockIdx.x;               // query tile (0..31)
    const int b  = blockIdx.y / NH;
    const int h  = blockIdx.y % NH;

    const float* qkv = g_qkv;
    const size_t base = (size_t)b * SS * QKV_W + (size_t)h * DH;

    // Load Q tile [64 x 64]
    {
        const float* src = qkv + base + (size_t)(qt * 64 + row) * QKV_W;
#pragma unroll
        for (int i = 0; i < 8; i++)
            *(float4*)&Qs[row][col0 + i * 4] = *(const float4*)&src[col0 + i * 4];
    }

    float o[64];
#pragma unroll
    for (int d = 0; d < 64; d++) o[d] = 0.f;
    float m_prev = -INFINITY, l = 0.f;
    const int qg = qt * 64 + row;
    const float scale = 0.125f;   // 1/sqrt(64)

    for (int kt = 0; kt <= qt; kt++) {
        __syncthreads();   // prev-iter PV reads of KVs done
        // Load K tile
        {
            const float* src = qkv + base + D_MODEL + (size_t)(kt * 64 + row) * QKV_W;
#pragma unroll
            for (int i = 0; i < 8; i++)
                *(float4*)&KVs[row][col0 + i * 4] = *(const float4*)&src[col0 + i * 4];
        }
        __syncthreads();   // Q + K visible

        // Scores: s[j] = Q[row] . K[col0+j]
        float s[32];
#pragma unroll
        for (int j = 0; j < 32; j++) s[j] = 0.f;
#pragma unroll 4
        for (int k4 = 0; k4 < 16; k4++) {
            float4 q = *(const float4*)&Qs[row][k4 * 4];
#pragma unroll
            for (int j = 0; j < 32; j++) {
                float4 kk = *(const float4*)&KVs[col0 + j][k4 * 4];
                s[j] = fmaf(q.x, kk.x, s[j]);
                s[j] = fmaf(q.y, kk.y, s[j]);
                s[j] = fmaf(q.z, kk.z, s[j]);
                s[j] = fmaf(q.w, kk.w, s[j]);
            }
        }

        // Causal mask + online softmax
        const int kbase = kt * 64 + col0;
        const bool diag = (kt == qt);
        float m_t = -INFINITY;
#pragma unroll
        for (int j = 0; j < 32; j++) {
            float sv = s[j] * scale;
            if (diag && (kbase + j > qg)) sv = -INFINITY;
            s[j] = sv;
            m_t = fmaxf(m_t, sv);
        }
        m_t = fmaxf(m_t, __shfl_xor_sync(0xffffffffu, m_t, 1));
        const float m_new = fmaxf(m_prev, m_t);
        float l_t = 0.f;
#pragma unroll
        for (int j = 0; j < 32; j++) {
            float p = __expf(s[j] - m_new);
            s[j] = p;
            l_t += p;
        }
        l_t += __shfl_xor_sync(0xffffffffu, l_t, 1);
        const float alpha = __expf(m_prev - m_new);
        l = l * alpha + l_t;
        m_prev = m_new;
#pragma unroll
        for (int d = 0; d < 64; d++) o[d] *= alpha;

        __syncthreads();   // score reads of K done
        // Load V tile into same buffer
        {
            const float* src = qkv + base + 2 * D_MODEL + (size_t)(kt * 64 + row) * QKV_W;
#pragma unroll
            for (int i = 0; i < 8; i++)
                *(float4*)&KVs[row][col0 + i * 4] = *(const float4*)&src[col0 + i * 4];
        }
        __syncthreads();   // V visible

        // o += P @ V (this thread's 32 key cols)
#pragma unroll 4
        for (int j = 0; j < 32; j++) {
            const float p = s[j];
            const float* vrow = &KVs[col0 + j][0];
#pragma unroll
            for (int d4 = 0; d4 < 16; d4++) {
                float4 v = *(const float4*)&vrow[d4 * 4];
                o[d4 * 4 + 0] = fmaf(p, v.x, o[d4 * 4 + 0]);
                o[d4 * 4 + 1] = fmaf(p, v.y, o[d4 * 4 + 1]);
                o[d4 * 4 + 2] = fmaf(p, v.z, o[d4 * 4 + 2]);
                o[d4 * 4 + 3] = fmaf(p, v.w, o[d4 * 4 + 3]);
            }
        }
    }

    // Combine the two half-threads and normalize
    const float inv_l = 1.f / l;
#pragma unroll
    for (int d = 0; d < 64; d++)
        o[d] += __shfl_xor_sync(0xffffffffu, o[d], 1);

    float* dst = g_att + ((size_t)b * SS + qt * 64 + row) * D_MODEL + h * DH;
#pragma unroll
    for (int i = 0; i < 8; i++) {
        float4 v;
        v.x = o[col0 + i * 4 + 0] * inv_l;
        v.y = o[col0 + i * 4 + 1] * inv_l;
        v.z = o[col0 + i * 4 + 2] * inv_l;
        v.w = o[col0 + i * 4 + 3] * inv_l;
        *(float4*)&dst[col0 + i * 4] = v;
    }
}

// ---------------------------------------------------------------------------
extern "C" void kernel_launch(void* const* d_in, const int* in_sizes, int n_in,
                              void* d_out, int out_size) {
    (void)in_sizes; (void)n_in; (void)out_size;
    const float* x     = (const float*)d_in[0];  // [2,2048,1024]
    const float* W_qkv = (const float*)d_in[1];  // [3072,1024]
    const float* b_qkv = (const float*)d_in[2];  // [3072]
    const float* W_out = (const float*)d_in[3];  // [1024,1024]
    const float* b_out = (const float*)d_in[4];  // [1024]
    float* out = (float*)d_out;                  // [2,2048,1024]

    float* qkv_buf = nullptr;
    float* att_buf = nullptr;
    cudaGetSymbolAddress((void**)&qkv_buf, g_qkv);
    cudaGetSymbolAddress((void**)&att_buf, g_att);

    // 1) QKV projection: [4096,1024] @ [3072,1024]^T + b -> [4096,3072]
    {
        dim3 grid(QKV_W / 128, MTOT / 128);
        sgemm_nt_bias<<<grid, 256>>>(x, W_qkv, b_qkv, qkv_buf,
                                     MTOT, QKV_W, D_MODEL);
    }
    // 2) Causal flash attention -> g_att [4096,1024]
    {
        dim3 grid(SS / 64, BB * NH);
        attn_kernel<<<grid, 128>>>();
    }
    // 3) Output projection: [4096,1024] @ [1024,1024]^T + b -> out
    {
        dim3 grid(D_MODEL / 128, MTOT / 128);
        sgemm_nt_bias<<<grid, 256>>>(att_buf, W_out, b_out, out,
                                     MTOT, D_MODEL, D_MODEL);
    }
}

// round 13
// speedup vs baseline: 1.9619x; 1.9619x over previous
#include <cuda_runtime.h>
#include <math.h>

#define D_MODEL 1024
#define NH 16
#define DH 64
#define BB 2
#define SS 2048
#define MTOT (BB * SS)          // 4096
#define QKV_W (3 * D_MODEL)     // 3072

// Scratch (device globals: allocation-free)
__device__ float g_qkv[(size_t)MTOT * QKV_W];    // [b, s, {q|k|v}, h, dh]
__device__ float g_att[(size_t)MTOT * D_MODEL];  // attention output pre-proj

// ---------------------------------------------------------------------------
// SGEMM: C[M,N] = A[M,K] @ W[N,K]^T + bias[N]
// BM=BN=128, BK=8, TM=TN=8, 256 threads. Global-load software pipeline:
// next k-slice LDG issued before the FMA block so DRAM/L2 latency hides
// under ~512 FMAs of compute.
// ---------------------------------------------------------------------------
__global__ __launch_bounds__(256)
void sgemm_nt_bias(const float* __restrict__ A, const float* __restrict__ W,
                   const float* __restrict__ bias, float* __restrict__ C,
                   int M, int N, int K) {
    __shared__ __align__(16) float As[8][132];
    __shared__ __align__(16) float Bs[8][132];

    const int tid = threadIdx.x;
    const int tx = tid & 15;
    const int ty = tid >> 4;
    const int bm = blockIdx.y * 128;
    const int bn = blockIdx.x * 128;

    const int lr = tid >> 1;
    const int lc = (tid & 1) * 4;

    float acc[8][8];
#pragma unroll
    for (int i = 0; i < 8; i++)
#pragma unroll
        for (int j = 0; j < 8; j++) acc[i][j] = 0.f;

    const float* Arow = A + (size_t)(bm + lr) * K + lc;
    const float* Wrow = W + (size_t)(bn + lr) * K + lc;

    float4 av = *(const float4*)(Arow);
    float4 wv = *(const float4*)(Wrow);

    for (int k0 = 0; k0 < K; k0 += 8) {
        As[lc + 0][lr] = av.x; As[lc + 1][lr] = av.y;
        As[lc + 2][lr] = av.z; As[lc + 3][lr] = av.w;
        Bs[lc + 0][lr] = wv.x; Bs[lc + 1][lr] = wv.y;
        Bs[lc + 2][lr] = wv.z; Bs[lc + 3][lr] = wv.w;
        __syncthreads();

        // Prefetch next k-slice while computing this one.
        if (k0 + 8 < K) {
            av = *(const float4*)(Arow + k0 + 8);
            wv = *(const float4*)(Wrow + k0 + 8);
        }

#pragma unroll
        for (int k = 0; k < 8; k++) {
            float ar[8], br[8];
            *(float4*)&ar[0] = *(const float4*)&As[k][ty * 8];
            *(float4*)&ar[4] = *(const float4*)&As[k][ty * 8 + 4];
            *(float4*)&br[0] = *(const float4*)&Bs[k][tx * 8];
            *(float4*)&br[4] = *(const float4*)&Bs[k][tx * 8 + 4];
#pragma unroll
            for (int i = 0; i < 8; i++)
#pragma unroll
                for (int j = 0; j < 8; j++)
                    acc[i][j] = fmaf(ar[i], br[j], acc[i][j]);
        }
        __syncthreads();
    }

#pragma unroll
    for (int i = 0; i < 8; i++) {
        float* crow = C + (size_t)(bm + ty * 8 + i) * N + bn + tx * 8;
        const float* brow = bias + bn + tx * 8;
#pragma unroll
        for (int j = 0; j < 8; j += 4) {
            float4 v;
            v.x = acc[i][j + 0] + brow[j + 0];
            v.y = acc[i][j + 1] + brow[j + 1];
            v.z = acc[i][j + 2] + brow[j + 2];
            v.w = acc[i][j + 3] + brow[j + 3];
            *(float4*)&crow[j] = v;
        }
    }
}

// ---------------------------------------------------------------------------
// Flash attention v2 (causal), fp32, GEMM-grade compute density.
// Block: 128 query rows of one (b,h), 256 threads (16x16).
// Score microtile 8q x 4k; PV microtile 8q x 4d. P via smem [q][k].
// Smem (dynamic, 86016 B):
//   Qs [64][132]  d-major  (Qs[d][q])
//   KV [64][68]   K: d-major Ks[d][k];  V: k-major Vs[k][d]  (shared buffer)
//   Ps [128][68]  q-major  (Ps[q][k])
// ---------------------------------------------------------------------------
#define QS_OFF 0
#define KV_OFF 8448
#define PS_OFF 12800
#define ATTN_SMEM_FLOATS 21504
#define ATTN_SMEM_BYTES (ATTN_SMEM_FLOATS * 4)

__global__ __launch_bounds__(256, 2)
void attn_kernel2() {
    extern __shared__ __align__(16) float smem[];
    float* Qs = smem + QS_OFF;
    float* KV = smem + KV_OFF;
    float* Ps = smem + PS_OFF;

    const int tid = threadIdx.x;
    const int tx = tid & 15;        // k (score) / d (PV) group
    const int ty = tid >> 4;        // q group
    const int qt = (int)(gridDim.x - 1) - (int)blockIdx.x;  // heavy tiles first
    const int b  = blockIdx.y >> 4;
    const int h  = blockIdx.y & 15;
    const size_t base = (size_t)b * SS * QKV_W + (size_t)h * DH;

    // Load + transpose Q tile [128 q x 64 d] -> Qs[d][q]
    {
        const int lr = tid >> 1;            // q row 0..127
        const int d0 = (tid & 1) * 32;
        const float* src = g_qkv + base + (size_t)(qt * 128 + lr) * QKV_W + d0;
#pragma unroll
        for (int i = 0; i < 8; i++) {
            float4 v = *(const float4*)(src + i * 4);
            Qs[(d0 + i * 4 + 0) * 132 + lr] = v.x;
            Qs[(d0 + i * 4 + 1) * 132 + lr] = v.y;
            Qs[(d0 + i * 4 + 2) * 132 + lr] = v.z;
            Qs[(d0 + i * 4 + 3) * 132 + lr] = v.w;
        }
    }

    float O[8][4];
#pragma unroll
    for (int i = 0; i < 8; i++)
#pragma unroll
        for (int j = 0; j < 4; j++) O[i][j] = 0.f;
    float m_prev[8], l[8];
#pragma unroll
    for (int i = 0; i < 8; i++) { m_prev[i] = -INFINITY; l[i] = 0.f; }

    const float scale = 0.125f;  // 1/sqrt(64)
    const int ktmax = 2 * qt + 1;

    for (int kt = 0; kt <= ktmax; kt++) {
        __syncthreads();  // prev PV reads of KV/Ps done (and Q visible on iter 0)

        // Load + transpose K tile [64 k x 64 d] -> KV[d][k]
        {
            const int lr = tid >> 2;            // k row 0..63
            const int d0 = (tid & 3) * 16;
            const float* src = g_qkv + base + D_MODEL +
                               (size_t)(kt * 64 + lr) * QKV_W + d0;
#pragma unroll
            for (int i = 0; i < 4; i++) {
                float4 v = *(const float4*)(src + i * 4);
                KV[(d0 + i * 4 + 0) * 68 + lr] = v.x;
                KV[(d0 + i * 4 + 1) * 68 + lr] = v.y;
                KV[(d0 + i * 4 + 2) * 68 + lr] = v.z;
                KV[(d0 + i * 4 + 3) * 68 + lr] = v.w;
            }
        }
        __syncthreads();  // Q + K visible

        // --- Score GEMM: acc[8][4] = Q[8q] . K[4k] over 64 d ---
        float acc[8][4];
#pragma unroll
        for (int i = 0; i < 8; i++)
#pragma unroll
            for (int j = 0; j < 4; j++) acc[i][j] = 0.f;

#pragma unroll 4
        for (int d = 0; d < 64; d++) {
            float4 q0 = *(const float4*)&Qs[d * 132 + ty * 8];
            float4 q1 = *(const float4*)&Qs[d * 132 + ty * 8 + 4];
            float4 kk = *(const float4*)&KV[d * 68 + tx * 4];
            float qr[8] = {q0.x, q0.y, q0.z, q0.w, q1.x, q1.y, q1.z, q1.w};
            float kr[4] = {kk.x, kk.y, kk.z, kk.w};
#pragma unroll
            for (int i = 0; i < 8; i++)
#pragma unroll
                for (int j = 0; j < 4; j++)
                    acc[i][j] = fmaf(qr[i], kr[j], acc[i][j]);
        }

        // --- Scale + causal mask ---
#pragma unroll
        for (int i = 0; i < 8; i++)
#pragma unroll
            for (int j = 0; j < 4; j++) acc[i][j] *= scale;

        if (kt >= 2 * qt) {   // only (partially) masked tiles
            const int qg = qt * 128 + ty * 8;
            const int kg = kt * 64 + tx * 4;
#pragma unroll
            for (int i = 0; i < 8; i++)
#pragma unroll
                for (int j = 0; j < 4; j++)
                    if (kg + j > qg + i) acc[i][j] = -INFINITY;
        }

        // --- Online softmax (per-row; tx lanes hold 4 cols each, reduce over 16 lanes) ---
        float alpha[8];
#pragma unroll
        for (int i = 0; i < 8; i++) {
            float mt = fmaxf(fmaxf(acc[i][0], acc[i][1]),
                             fmaxf(acc[i][2], acc[i][3]));
            mt = fmaxf(mt, __shfl_xor_sync(0xffffffffu, mt, 1));
            mt = fmaxf(mt, __shfl_xor_sync(0xffffffffu, mt, 2));
            mt = fmaxf(mt, __shfl_xor_sync(0xffffffffu, mt, 4));
            mt = fmaxf(mt, __shfl_xor_sync(0xffffffffu, mt, 8));
            const float m_new = fmaxf(m_prev[i], mt);
            alpha[i] = __expf(m_prev[i] - m_new);
            float lt = 0.f;
#pragma unroll
            for (int j = 0; j < 4; j++) {
                float p = __expf(acc[i][j] - m_new);
                acc[i][j] = p;
                lt += p;
            }
            lt += __shfl_xor_sync(0xffffffffu, lt, 1);
            lt += __shfl_xor_sync(0xffffffffu, lt, 2);
            lt += __shfl_xor_sync(0xffffffffu, lt, 4);
            lt += __shfl_xor_sync(0xffffffffu, lt, 8);
            l[i] = l[i] * alpha[i] + lt;
            m_prev[i] = m_new;
        }

        // Rescale running O, write P to smem [q][k]
#pragma unroll
        for (int i = 0; i < 8; i++) {
#pragma unroll
            for (int j = 0; j < 4; j++) O[i][j] *= alpha[i];
            float4 pv = make_float4(acc[i][0], acc[i][1], acc[i][2], acc[i][3]);
            *(float4*)&Ps[(ty * 8 + i) * 68 + tx * 4] = pv;
        }
        __syncthreads();  // Ps visible; score-GEMM reads of KV(K) done

        // Load V tile [64 k x 64 d] -> KV[k][d] (natural layout)
        {
            const int lr = tid >> 2;            // k row
            const int d0 = (tid & 3) * 16;
            const float* src = g_qkv + base + 2 * D_MODEL +
                               (size_t)(kt * 64 + lr) * QKV_W + d0;
#pragma unroll
            for (int i = 0; i < 4; i++)
                *(float4*)&KV[lr * 68 + d0 + i * 4] = *(const float4*)(src + i * 4);
        }
        __syncthreads();  // V visible

        // --- PV GEMM: O[8q][4d] += P[8q][64k] @ V[64k][4d] ---
#pragma unroll 2
        for (int k4 = 0; k4 < 16; k4++) {
            float4 p[8];
#pragma unroll
            for (int i = 0; i < 8; i++)
                p[i] = *(const float4*)&Ps[(ty * 8 + i) * 68 + k4 * 4];
            float4 v0 = *(const float4*)&KV[(k4 * 4 + 0) * 68 + tx * 4];
            float4 v1 = *(const float4*)&KV[(k4 * 4 + 1) * 68 + tx * 4];
            float4 v2 = *(const float4*)&KV[(k4 * 4 + 2) * 68 + tx * 4];
            float4 v3 = *(const float4*)&KV[(k4 * 4 + 3) * 68 + tx * 4];
#pragma unroll
            for (int i = 0; i < 8; i++) {
                O[i][0] = fmaf(p[i].x, v0.x, O[i][0]);
                O[i][1] = fmaf(p[i].x, v0.y, O[i][1]);
                O[i][2] = fmaf(p[i].x, v0.z, O[i][2]);
                O[i][3] = fmaf(p[i].x, v0.w, O[i][3]);
                O[i][0] = fmaf(p[i].y, v1.x, O[i][0]);
                O[i][1] = fmaf(p[i].y, v1.y, O[i][1]);
                O[i][2] = fmaf(p[i].y, v1.z, O[i][2]);
                O[i][3] = fmaf(p[i].y, v1.w, O[i][3]);
                O[i][0] = fmaf(p[i].z, v2.x, O[i][0]);
                O[i][1] = fmaf(p[i].z, v2.y, O[i][1]);
                O[i][2] = fmaf(p[i].z, v2.z, O[i][2]);
                O[i][3] = fmaf(p[i].z, v2.w, O[i][3]);
                O[i][0] = fmaf(p[i].w, v3.x, O[i][0]);
                O[i][1] = fmaf(p[i].w, v3.y, O[i][1]);
                O[i][2] = fmaf(p[i].w, v3.z, O[i][2]);
                O[i][3] = fmaf(p[i].w, v3.w, O[i][3]);
            }
        }
    }

    // --- Epilogue: normalize and store to g_att ---
#pragma unroll
    for (int i = 0; i < 8; i++) {
        const float inv_l = 1.f / l[i];
        float* dst = g_att + ((size_t)b * SS + qt * 128 + ty * 8 + i) * D_MODEL
                     + h * DH + tx * 4;
        float4 v;
        v.x = O[i][0] * inv_l;
        v.y = O[i][1] * inv_l;
        v.z = O[i][2] * inv_l;
        v.w = O[i][3] * inv_l;
        *(float4*)dst = v;
    }
}

// ---------------------------------------------------------------------------
extern "C" void kernel_launch(void* const* d_in, const int* in_sizes, int n_in,
                              void* d_out, int out_size) {
    (void)in_sizes; (void)n_in; (void)out_size;
    const float* x     = (const float*)d_in[0];
    const float* W_qkv = (const float*)d_in[1];
    const float* b_qkv = (const float*)d_in[2];
    const float* W_out = (const float*)d_in[3];
    const float* b_out = (const float*)d_in[4];
    float* out = (float*)d_out;

    float* qkv_buf = nullptr;
    float* att_buf = nullptr;
    cudaGetSymbolAddress((void**)&qkv_buf, g_qkv);
    cudaGetSymbolAddress((void**)&att_buf, g_att);

    // Idempotent host-side attribute set (no static guard: harness requires
    // deterministic, guard-free kernel_launch).
    cudaFuncSetAttribute(attn_kernel2,
                         cudaFuncAttributeMaxDynamicSharedMemorySize,
                         ATTN_SMEM_BYTES);

    // 1) QKV projection
    {
        dim3 grid(QKV_W / 128, MTOT / 128);
        sgemm_nt_bias<<<grid, 256>>>(x, W_qkv, b_qkv, qkv_buf,
                                     MTOT, QKV_W, D_MODEL);
    }
    // 2) Causal flash attention
    {
        dim3 grid(SS / 128, BB * NH);
        attn_kernel2<<<grid, 256, ATTN_SMEM_BYTES>>>();
    }
    // 3) Output projection
    {
        dim3 grid(D_MODEL / 128, MTOT / 128);
        sgemm_nt_bias<<<grid, 256>>>(att_buf, W_out, b_out, out,
                                     MTOT, D_MODEL, D_MODEL);
    }
}